// round 2
// baseline (speedup 1.0000x reference)
#include <cuda_runtime.h>
#include <cuda_bf16.h>
#include <cstdint>

// Problem constants
#define BB   16
#define CC   384      // C
#define CO   1536     // EXP*C
#define HW   1024     // 32*32
#define EMB_ 1024
#define NG   32       // groups
#define CPG  12       // channels per group
#define EPS_ 1e-5f

// Scratch (device globals; no cudaMalloc allowed)
__device__ __align__(16) float g_A[BB * CC];      // rstd*gn_w per (b,c)
__device__ __align__(16) float g_D[BB * CC];      // gn_b - mu*rstd*gn_w
__device__ __align__(16) float g_S[BB * CO];      // 1 + scale
__device__ __align__(16) float g_T[BB * CO];      // shift
__device__ __align__(16) float g_B1[BB * CO];     // b1 + w1 @ D
__device__ __align__(16) float g_H[(size_t)BB * CO * HW];  // 96 MB intermediate

__device__ __forceinline__ uint32_t f2tf32(float x) {
    uint32_t r;
    asm("cvt.rna.tf32.f32 %0, %1;" : "=r"(r) : "f"(x));
    return r;
}

#define MMA_TF32(d, a, b)                                                     \
    asm volatile(                                                             \
        "mma.sync.aligned.m16n8k8.row.col.f32.tf32.tf32.f32 "                 \
        "{%0,%1,%2,%3},{%4,%5,%6,%7},{%8,%9},{%0,%1,%2,%3};\n"                \
        : "+f"((d)[0]), "+f"((d)[1]), "+f"((d)[2]), "+f"((d)[3])              \
        : "r"((a)[0]), "r"((a)[1]), "r"((a)[2]), "r"((a)[3]),                 \
          "r"((b)[0]), "r"((b)[1]))

// ---------------------------------------------------------------------------
// K1: GroupNorm statistics -> per-channel affine (A, D)
// grid: B*NG blocks, 256 threads. Group data is contiguous: 12*1024 floats.
// ---------------------------------------------------------------------------
__global__ void k_gnstats(const float* __restrict__ x,
                          const float* __restrict__ gnw,
                          const float* __restrict__ gnb) {
    int bg = blockIdx.x;
    int b = bg >> 5;
    int gi = bg & 31;
    const float4* p = (const float4*)(x + ((size_t)b * CC + (size_t)gi * CPG) * HW);
    float s = 0.f, ss = 0.f;
#pragma unroll
    for (int i = 0; i < 12; i++) {
        float4 v = p[threadIdx.x + i * 256];
        s  += v.x + v.y + v.z + v.w;
        ss += v.x * v.x + v.y * v.y + v.z * v.z + v.w * v.w;
    }
#pragma unroll
    for (int off = 16; off; off >>= 1) {
        s  += __shfl_xor_sync(0xffffffffu, s, off);
        ss += __shfl_xor_sync(0xffffffffu, ss, off);
    }
    __shared__ float sh[64];
    int w = threadIdx.x >> 5, l = threadIdx.x & 31;
    if (l == 0) { sh[w] = s; sh[32 + w] = ss; }
    __syncthreads();
    if (threadIdx.x < CPG) {
        float S = 0.f, SS = 0.f;
#pragma unroll
        for (int i = 0; i < 8; i++) { S += sh[i]; SS += sh[32 + i]; }
        float mean = S * (1.0f / 12288.0f);
        float var  = SS * (1.0f / 12288.0f) - mean * mean;
        float rstd = rsqrtf(var + EPS_);
        int cch = gi * CPG + threadIdx.x;
        float wv = gnw[cch], bv = gnb[cch];
        g_A[b * CC + cch] = rstd * wv;
        g_D[b * CC + cch] = bv - mean * rstd * wv;
    }
}

// ---------------------------------------------------------------------------
// K2: emb_out = emb @ we.T + be  -> S = 1+scale, T = shift
// warp per (b,o); 3072 blocks * 8 warps = 24576 tasks
// ---------------------------------------------------------------------------
__global__ void k_emb(const float* __restrict__ emb,
                      const float* __restrict__ we,
                      const float* __restrict__ be) {
    int task = blockIdx.x * 8 + (threadIdx.x >> 5);
    int lane = threadIdx.x & 31;
    int b = task / CO;
    int o = task - b * CO;
    const float4* e4 = (const float4*)(emb + (size_t)b * EMB_);
    const float4* wa = (const float4*)(we + (size_t)o * EMB_);
    const float4* wb = (const float4*)(we + (size_t)(o + CO) * EMB_);
    float s1 = 0.f, s2 = 0.f;
#pragma unroll
    for (int i = 0; i < 8; i++) {
        float4 ev = e4[lane + i * 32];
        float4 va = wa[lane + i * 32];
        float4 vb = wb[lane + i * 32];
        s1 += ev.x * va.x + ev.y * va.y + ev.z * va.z + ev.w * va.w;
        s2 += ev.x * vb.x + ev.y * vb.y + ev.z * vb.z + ev.w * vb.w;
    }
#pragma unroll
    for (int off = 16; off; off >>= 1) {
        s1 += __shfl_xor_sync(0xffffffffu, s1, off);
        s2 += __shfl_xor_sync(0xffffffffu, s2, off);
    }
    if (lane == 0) {
        g_S[task] = 1.0f + s1 + be[o];
        g_T[task] = s2 + be[o + CO];
    }
}

// ---------------------------------------------------------------------------
// K2b: b1'[b,o] = b1[o] + sum_c w1[o,c] * D[b,c]
// ---------------------------------------------------------------------------
__global__ void k_biasfold(const float* __restrict__ w1,
                           const float* __restrict__ b1) {
    int task = blockIdx.x * 8 + (threadIdx.x >> 5);
    int lane = threadIdx.x & 31;
    int b = task / CO;
    int o = task - b * CO;
    const float* wr = w1 + (size_t)o * CC;
    const float* dr = g_D + b * CC;
    float s = 0.f;
#pragma unroll
    for (int i = 0; i < 12; i++) {
        int c = lane + i * 32;
        s += wr[c] * dr[c];
    }
#pragma unroll
    for (int off = 16; off; off >>= 1)
        s += __shfl_xor_sync(0xffffffffu, s, off);
    if (lane == 0) g_B1[task] = b1[o] + s;
}

// ---------------------------------------------------------------------------
// K3: GEMM1. Per batch: H = modulate(silu(W1 @ (A.x) + b1'))
// M=1536 (o), N=1024 (s), K=384 (c). CTA tile 128x128, BK=16.
// 8 warps (4x2), warp tile 32x64, mma m16n8k8 tf32.
// ---------------------------------------------------------------------------
__global__ void __launch_bounds__(256, 1)
k_gemm1(const float* __restrict__ x,
        const float* __restrict__ w1) {
    __shared__ uint32_t As[128 * 20];   // stride 20: conflict-free frag loads
    __shared__ uint32_t Bs[16 * 136];   // stride 136
    int b = blockIdx.z;
    int tm = blockIdx.y, tn = blockIdx.x;
    int tid = threadIdx.x, lane = tid & 31, warp = tid >> 5;
    int wm = warp & 3, wn = warp >> 2;
    int g = lane >> 2, t = lane & 3;

    float acc[2][8][4];
#pragma unroll
    for (int i = 0; i < 2; i++)
#pragma unroll
        for (int j = 0; j < 8; j++)
#pragma unroll
            for (int e = 0; e < 4; e++) acc[i][j][e] = 0.f;

    // Per-thread load coordinates (hoisted)
    int arow = tid >> 2, aq = tid & 3;                 // A: 64 rows per pass
    int brow = tid >> 5, bq = tid & 31;                // B: 8 rows per pass
    const float* AgBase = w1 + (size_t)tm * 128 * CC + (size_t)arow * CC + aq * 4;
    const float* BgBase = x + (size_t)b * CC * HW + (size_t)tn * 128
                            + (size_t)brow * HW + bq * 4;
    const float* Av = g_A + b * CC;

    for (int kt = 0; kt < CC / 16; kt++) {
        // A tile: 128x16 of w1 (row-major, stride CC)
#pragma unroll
        for (int i = 0; i < 2; i++) {
            float4 v = *(const float4*)(AgBase + (size_t)(i * 64) * CC + kt * 16);
            uint32_t* d = &As[(arow + i * 64) * 20 + aq * 4];
            d[0] = f2tf32(v.x); d[1] = f2tf32(v.y);
            d[2] = f2tf32(v.z); d[3] = f2tf32(v.w);
        }
        // B tile: 16x128 of x, scaled by A[c] (GN fold)
#pragma unroll
        for (int i = 0; i < 2; i++) {
            int row = brow + i * 8;
            float a = Av[kt * 16 + row];
            float4 v = *(const float4*)(BgBase + (size_t)(kt * 16 + i * 8) * HW);
            uint32_t* d = &Bs[row * 136 + bq * 4];
            d[0] = f2tf32(v.x * a); d[1] = f2tf32(v.y * a);
            d[2] = f2tf32(v.z * a); d[3] = f2tf32(v.w * a);
        }
        __syncthreads();
#pragma unroll
        for (int kk = 0; kk < 16; kk += 8) {
            uint32_t af[2][4], bf[8][2];
#pragma unroll
            for (int mt = 0; mt < 2; mt++) {
                int r = wm * 32 + mt * 16 + g;
                af[mt][0] = As[r * 20 + kk + t];
                af[mt][1] = As[(r + 8) * 20 + kk + t];
                af[mt][2] = As[r * 20 + kk + t + 4];
                af[mt][3] = As[(r + 8) * 20 + kk + t + 4];
            }
#pragma unroll
            for (int nt = 0; nt < 8; nt++) {
                int cc = wn * 64 + nt * 8 + g;
                bf[nt][0] = Bs[(kk + t) * 136 + cc];
                bf[nt][1] = Bs[(kk + t + 4) * 136 + cc];
            }
#pragma unroll
            for (int mt = 0; mt < 2; mt++)
#pragma unroll
                for (int nt = 0; nt < 8; nt++)
                    MMA_TF32(acc[mt][nt], af[mt], bf[nt]);
        }
        __syncthreads();
    }

    // Epilogue: +b1', silu, modulate, store H
    float* Hb = g_H + (size_t)b * CO * HW;
    int row0 = tm * 128 + wm * 32;
    int col0 = tn * 128 + wn * 64;
#pragma unroll
    for (int mt = 0; mt < 2; mt++)
#pragma unroll
        for (int h2 = 0; h2 < 2; h2++) {
            int o = row0 + mt * 16 + h2 * 8 + g;
            int idx = b * CO + o;
            float b1v = g_B1[idx], sv = g_S[idx], tv = g_T[idx];
#pragma unroll
            for (int nt = 0; nt < 8; nt++) {
                int sc = col0 + nt * 8 + t * 2;
#pragma unroll
                for (int e = 0; e < 2; e++) {
                    float v = acc[mt][nt][h2 * 2 + e] + b1v;
                    float hh = v / (1.0f + __expf(-v));   // silu
                    Hb[(size_t)o * HW + sc + e] = hh * sv + tv;
                }
            }
        }
}

// ---------------------------------------------------------------------------
// K4: GEMM2. Per batch: out = W2 @ H + b2 + x
// M=384 (o), N=1024 (s), K=1536.
// ---------------------------------------------------------------------------
__global__ void __launch_bounds__(256, 1)
k_gemm2(const float* __restrict__ w2,
        const float* __restrict__ b2,
        const float* __restrict__ x,
        float* __restrict__ out) {
    __shared__ uint32_t As[128 * 20];
    __shared__ uint32_t Bs[16 * 136];
    int b = blockIdx.z;
    int tm = blockIdx.y, tn = blockIdx.x;
    int tid = threadIdx.x, lane = tid & 31, warp = tid >> 5;
    int wm = warp & 3, wn = warp >> 2;
    int g = lane >> 2, t = lane & 3;

    float acc[2][8][4];
#pragma unroll
    for (int i = 0; i < 2; i++)
#pragma unroll
        for (int j = 0; j < 8; j++)
#pragma unroll
            for (int e = 0; e < 4; e++) acc[i][j][e] = 0.f;

    int arow = tid >> 2, aq = tid & 3;
    int brow = tid >> 5, bq = tid & 31;
    const float* AgBase = w2 + (size_t)tm * 128 * CO + (size_t)arow * CO + aq * 4;
    const float* BgBase = g_H + (size_t)b * CO * HW + (size_t)tn * 128
                              + (size_t)brow * HW + bq * 4;

    for (int kt = 0; kt < CO / 16; kt++) {
#pragma unroll
        for (int i = 0; i < 2; i++) {
            float4 v = *(const float4*)(AgBase + (size_t)(i * 64) * CO + kt * 16);
            uint32_t* d = &As[(arow + i * 64) * 20 + aq * 4];
            d[0] = f2tf32(v.x); d[1] = f2tf32(v.y);
            d[2] = f2tf32(v.z); d[3] = f2tf32(v.w);
        }
#pragma unroll
        for (int i = 0; i < 2; i++) {
            int row = brow + i * 8;
            float4 v = *(const float4*)(BgBase + (size_t)(kt * 16 + i * 8) * HW);
            uint32_t* d = &Bs[row * 136 + bq * 4];
            d[0] = f2tf32(v.x); d[1] = f2tf32(v.y);
            d[2] = f2tf32(v.z); d[3] = f2tf32(v.w);
        }
        __syncthreads();
#pragma unroll
        for (int kk = 0; kk < 16; kk += 8) {
            uint32_t af[2][4], bf[8][2];
#pragma unroll
            for (int mt = 0; mt < 2; mt++) {
                int r = wm * 32 + mt * 16 + g;
                af[mt][0] = As[r * 20 + kk + t];
                af[mt][1] = As[(r + 8) * 20 + kk + t];
                af[mt][2] = As[r * 20 + kk + t + 4];
                af[mt][3] = As[(r + 8) * 20 + kk + t + 4];
            }
#pragma unroll
            for (int nt = 0; nt < 8; nt++) {
                int cc = wn * 64 + nt * 8 + g;
                bf[nt][0] = Bs[(kk + t) * 136 + cc];
                bf[nt][1] = Bs[(kk + t + 4) * 136 + cc];
            }
#pragma unroll
            for (int mt = 0; mt < 2; mt++)
#pragma unroll
                for (int nt = 0; nt < 8; nt++)
                    MMA_TF32(acc[mt][nt], af[mt], bf[nt]);
        }
        __syncthreads();
    }

    // Epilogue: +b2 + residual x, write out
    const float* xb = x + (size_t)b * CC * HW;
    float* ob = out + (size_t)b * CC * HW;
    int row0 = tm * 128 + wm * 32;
    int col0 = tn * 128 + wn * 64;
#pragma unroll
    for (int mt = 0; mt < 2; mt++)
#pragma unroll
        for (int h2 = 0; h2 < 2; h2++) {
            int o = row0 + mt * 16 + h2 * 8 + g;
            float b2v = b2[o];
#pragma unroll
            for (int nt = 0; nt < 8; nt++) {
                int sc = col0 + nt * 8 + t * 2;
#pragma unroll
                for (int e = 0; e < 2; e++) {
                    float v = acc[mt][nt][h2 * 2 + e] + b2v
                              + xb[(size_t)o * HW + sc + e];
                    ob[(size_t)o * HW + sc + e] = v;
                }
            }
        }
}

// ---------------------------------------------------------------------------
extern "C" void kernel_launch(void* const* d_in, const int* in_sizes, int n_in,
                              void* d_out, int out_size) {
    const float* x    = (const float*)d_in[0];
    const float* emb  = (const float*)d_in[1];
    const float* gn_w = (const float*)d_in[2];
    const float* gn_b = (const float*)d_in[3];
    const float* w1   = (const float*)d_in[4];
    const float* b1   = (const float*)d_in[5];
    const float* we   = (const float*)d_in[6];
    const float* be   = (const float*)d_in[7];
    const float* w2   = (const float*)d_in[8];
    const float* b2   = (const float*)d_in[9];
    float* out = (float*)d_out;

    k_gnstats<<<BB * NG, 256>>>(x, gn_w, gn_b);
    k_emb<<<(BB * CO) / 8, 256>>>(emb, we, be);
    k_biasfold<<<(BB * CO) / 8, 256>>>(w1, b1);
    k_gemm1<<<dim3(HW / 128, CO / 128, BB), 256>>>(x, w1);
    k_gemm2<<<dim3(HW / 128, CC / 128, BB), 256>>>(w2, b2, x, out);
}

// round 3
// speedup vs baseline: 1.9433x; 1.9433x over previous
#include <cuda_runtime.h>
#include <cuda_bf16.h>
#include <cstdint>

// Problem constants
#define BB   16
#define CC   384      // C
#define CO   1536     // EXP*C
#define HW   1024     // 32*32
#define EMB_ 1024
#define NG   32
#define CPG  12
#define EPS_ 1e-5f

#define STAGES 4
#define AS_U   (128 * 20)          // A tile: 128 rows x 16 tf32 + pad4
#define BS_U   (16 * 136)          // B tile: 16 rows x 128 tf32 + pad8
#define STG_U  (AS_U + BS_U)       // uints per stage (4736 -> 18944 B)
#define SMEM_BYTES (STAGES * STG_U * 4)

// Scratch (device globals; no cudaMalloc allowed)
__device__ __align__(16) float    g_A[BB * CC];
__device__ __align__(16) float    g_D[BB * CC];
__device__ __align__(16) float    g_S[BB * CO];
__device__ __align__(16) float    g_T[BB * CO];
__device__ __align__(16) uint32_t g_W1t[CO * CC];               // tf32 w1
__device__ __align__(16) uint32_t g_W2t[CC * CO];               // tf32 w2
__device__ __align__(16) uint32_t g_Xn[(size_t)BB * CC * HW];   // tf32 normed x (25MB)
__device__ __align__(16) uint32_t g_H[(size_t)BB * CO * HW];    // tf32 hidden (96MB)

__device__ __forceinline__ uint32_t f2tf32(float x) {
    uint32_t r;
    asm("cvt.rna.tf32.f32 %0, %1;" : "=r"(r) : "f"(x));
    return r;
}

__device__ __forceinline__ void cpa16(uint32_t dst, const void* src) {
    asm volatile("cp.async.cg.shared.global [%0], [%1], 16;" :: "r"(dst), "l"(src));
}
#define CP_COMMIT() asm volatile("cp.async.commit_group;")
#define CP_WAIT3()  asm volatile("cp.async.wait_group 3;")

#define MMA_TF32(d, a, b)                                                     \
    asm volatile(                                                             \
        "mma.sync.aligned.m16n8k8.row.col.f32.tf32.tf32.f32 "                 \
        "{%0,%1,%2,%3},{%4,%5,%6,%7},{%8,%9},{%0,%1,%2,%3};\n"                \
        : "+f"((d)[0]), "+f"((d)[1]), "+f"((d)[2]), "+f"((d)[3])              \
        : "r"((a)[0]), "r"((a)[1]), "r"((a)[2]), "r"((a)[3]),                 \
          "r"((b)[0]), "r"((b)[1]))

// ---------------------------------------------------------------------------
// K1: GroupNorm stats -> per-channel affine (A, D)
// ---------------------------------------------------------------------------
__global__ void k_gnstats(const float* __restrict__ x,
                          const float* __restrict__ gnw,
                          const float* __restrict__ gnb) {
    int bg = blockIdx.x;
    int b = bg >> 5;
    int gi = bg & 31;
    const float4* p = (const float4*)(x + ((size_t)b * CC + (size_t)gi * CPG) * HW);
    float s = 0.f, ss = 0.f;
#pragma unroll
    for (int i = 0; i < 12; i++) {
        float4 v = p[threadIdx.x + i * 256];
        s  += v.x + v.y + v.z + v.w;
        ss += v.x * v.x + v.y * v.y + v.z * v.z + v.w * v.w;
    }
#pragma unroll
    for (int off = 16; off; off >>= 1) {
        s  += __shfl_xor_sync(0xffffffffu, s, off);
        ss += __shfl_xor_sync(0xffffffffu, ss, off);
    }
    __shared__ float sh[64];
    int w = threadIdx.x >> 5, l = threadIdx.x & 31;
    if (l == 0) { sh[w] = s; sh[32 + w] = ss; }
    __syncthreads();
    if (threadIdx.x < CPG) {
        float S = 0.f, SS = 0.f;
#pragma unroll
        for (int i = 0; i < 8; i++) { S += sh[i]; SS += sh[32 + i]; }
        float mean = S * (1.0f / 12288.0f);
        float var  = SS * (1.0f / 12288.0f) - mean * mean;
        float rstd = rsqrtf(var + EPS_);
        int cch = gi * CPG + threadIdx.x;
        float wv = gnw[cch], bv = gnb[cch];
        g_A[b * CC + cch] = rstd * wv;
        g_D[b * CC + cch] = bv - mean * rstd * wv;
    }
}

// ---------------------------------------------------------------------------
// K2: emb_out = emb @ we.T + be  -> S = 1+scale, T = shift
// ---------------------------------------------------------------------------
__global__ void k_emb(const float* __restrict__ emb,
                      const float* __restrict__ we,
                      const float* __restrict__ be) {
    int task = blockIdx.x * 8 + (threadIdx.x >> 5);
    int lane = threadIdx.x & 31;
    int b = task / CO;
    int o = task - b * CO;
    const float4* e4 = (const float4*)(emb + (size_t)b * EMB_);
    const float4* wa = (const float4*)(we + (size_t)o * EMB_);
    const float4* wb = (const float4*)(we + (size_t)(o + CO) * EMB_);
    float s1 = 0.f, s2 = 0.f;
#pragma unroll
    for (int i = 0; i < 8; i++) {
        float4 ev = e4[lane + i * 32];
        float4 va = wa[lane + i * 32];
        float4 vb = wb[lane + i * 32];
        s1 += ev.x * va.x + ev.y * va.y + ev.z * va.z + ev.w * va.w;
        s2 += ev.x * vb.x + ev.y * vb.y + ev.z * vb.z + ev.w * vb.w;
    }
#pragma unroll
    for (int off = 16; off; off >>= 1) {
        s1 += __shfl_xor_sync(0xffffffffu, s1, off);
        s2 += __shfl_xor_sync(0xffffffffu, s2, off);
    }
    if (lane == 0) {
        g_S[task] = 1.0f + s1 + be[o];
        g_T[task] = s2 + be[o + CO];
    }
}

// ---------------------------------------------------------------------------
// K3: weights -> tf32 (one pass for w1 and w2)
// ---------------------------------------------------------------------------
__global__ void k_prep(const float* __restrict__ w1,
                       const float* __restrict__ w2) {
    const int N1 = CO * CC / 4;          // float4 count of w1
    int t = blockIdx.x * blockDim.x + threadIdx.x;
    const float4* src = (t < N1) ? (const float4*)w1 : (const float4*)w2;
    uint4* dst = (t < N1) ? (uint4*)g_W1t : (uint4*)g_W2t;
    int i = (t < N1) ? t : t - N1;
    float4 v = src[i];
    uint4 o;
    o.x = f2tf32(v.x); o.y = f2tf32(v.y); o.z = f2tf32(v.z); o.w = f2tf32(v.w);
    dst[i] = o;
}

// ---------------------------------------------------------------------------
// K4: xn = round_tf32(A*x + D)
// ---------------------------------------------------------------------------
__global__ void k_norm(const float* __restrict__ x) {
    int t = blockIdx.x * blockDim.x + threadIdx.x;     // float4 index
    int cl = t >> 8;                                   // b*CC + c  (HW/4 = 256)
    float a = g_A[cl], d = g_D[cl];
    float4 v = ((const float4*)x)[t];
    uint4 o;
    o.x = f2tf32(fmaf(a, v.x, d));
    o.y = f2tf32(fmaf(a, v.y, d));
    o.z = f2tf32(fmaf(a, v.z, d));
    o.w = f2tf32(fmaf(a, v.w, d));
    ((uint4*)g_Xn)[t] = o;
}

// ---------------------------------------------------------------------------
// Shared GEMM mainloop (cp.async 4-stage, 128x128 CTA tile, BK=16)
// ---------------------------------------------------------------------------
struct Frag { float acc[2][8][4]; };

template <int KT>
__device__ __forceinline__ void gemm_mainloop(
        uint32_t* sm, const uint32_t* Ag, int lda,
        const uint32_t* Bg, Frag& fr,
        int wm, int wn, int g, int t, int tid) {
#pragma unroll
    for (int i = 0; i < 2; i++)
#pragma unroll
        for (int j = 0; j < 8; j++)
#pragma unroll
            for (int e = 0; e < 4; e++) fr.acc[i][j][e] = 0.f;

    int arow = tid >> 2, aq = tid & 3;
    int brow = tid >> 5, bq = tid & 31;
    const uint32_t* Ab = Ag + (size_t)arow * lda + aq * 4;
    const uint32_t* Bb = Bg + (size_t)brow * HW + bq * 4;

    uint32_t sbase = (uint32_t)__cvta_generic_to_shared(sm);
    uint32_t sA = sbase + (arow * 20 + aq * 4) * 4;
    uint32_t sB = sbase + (AS_U + brow * 136 + bq * 4) * 4;

    // prologue: stages 0..STAGES-2
#pragma unroll
    for (int s = 0; s < STAGES - 1; s++) {
        uint32_t off = s * STG_U * 4;
        cpa16(sA + off,             Ab + s * 16);
        cpa16(sA + off + 64 * 80,   Ab + (size_t)64 * lda + s * 16);
        cpa16(sB + off,             Bb + (size_t)(s * 16) * HW);
        cpa16(sB + off + 8 * 544,   Bb + (size_t)(s * 16 + 8) * HW);
        CP_COMMIT();
    }

    for (int kt = 0; kt < KT; kt++) {
        if (kt + STAGES - 1 < KT) {
            int s = (kt + STAGES - 1) % STAGES;
            int k = kt + STAGES - 1;
            uint32_t off = s * STG_U * 4;
            cpa16(sA + off,             Ab + k * 16);
            cpa16(sA + off + 64 * 80,   Ab + (size_t)64 * lda + k * 16);
            cpa16(sB + off,             Bb + (size_t)(k * 16) * HW);
            cpa16(sB + off + 8 * 544,   Bb + (size_t)(k * 16 + 8) * HW);
        }
        CP_COMMIT();
        CP_WAIT3();
        __syncthreads();

        const uint32_t* As = sm + (kt % STAGES) * STG_U;
        const uint32_t* Bs = As + AS_U;
#pragma unroll
        for (int kk = 0; kk < 16; kk += 8) {
            uint32_t af[2][4], bf[8][2];
#pragma unroll
            for (int mt = 0; mt < 2; mt++) {
                int r = wm * 32 + mt * 16 + g;
                af[mt][0] = As[r * 20 + kk + t];
                af[mt][1] = As[(r + 8) * 20 + kk + t];
                af[mt][2] = As[r * 20 + kk + t + 4];
                af[mt][3] = As[(r + 8) * 20 + kk + t + 4];
            }
#pragma unroll
            for (int nt = 0; nt < 8; nt++) {
                int cc = wn * 64 + nt * 8 + g;
                bf[nt][0] = Bs[(kk + t) * 136 + cc];
                bf[nt][1] = Bs[(kk + t + 4) * 136 + cc];
            }
#pragma unroll
            for (int mt = 0; mt < 2; mt++)
#pragma unroll
                for (int nt = 0; nt < 8; nt++)
                    MMA_TF32(fr.acc[mt][nt], af[mt], bf[nt]);
        }
        __syncthreads();
    }
}

// ---------------------------------------------------------------------------
// K5: GEMM1. H = round_tf32(modulate(silu(W1 @ xn + b1)))
// ---------------------------------------------------------------------------
extern __shared__ uint32_t dyn_smem[];

__global__ void __launch_bounds__(256, 2)
k_gemm1(const float* __restrict__ b1) {
    int b = blockIdx.z, tm = blockIdx.y, tn = blockIdx.x;
    int tid = threadIdx.x, lane = tid & 31, warp = tid >> 5;
    int wm = warp & 3, wn = warp >> 2;
    int g = lane >> 2, t = lane & 3;

    const uint32_t* Ag = g_W1t + (size_t)tm * 128 * CC;
    const uint32_t* Bg = g_Xn + (size_t)b * CC * HW + (size_t)tn * 128;

    Frag fr;
    gemm_mainloop<CC / 16>(dyn_smem, Ag, CC, Bg, fr, wm, wn, g, t, tid);

    uint32_t* Hb = g_H + (size_t)b * CO * HW;
    int row0 = tm * 128 + wm * 32;
    int col0 = tn * 128 + wn * 64;
#pragma unroll
    for (int mt = 0; mt < 2; mt++)
#pragma unroll
        for (int h2 = 0; h2 < 2; h2++) {
            int o = row0 + mt * 16 + h2 * 8 + g;
            int idx = b * CO + o;
            float b1v = b1[o], sv = g_S[idx], tv = g_T[idx];
#pragma unroll
            for (int nt = 0; nt < 8; nt++) {
                int sc = col0 + nt * 8 + t * 2;
                float v0 = fr.acc[mt][nt][h2 * 2 + 0] + b1v;
                float v1 = fr.acc[mt][nt][h2 * 2 + 1] + b1v;
                float h0 = v0 / (1.0f + __expf(-v0));
                float h1 = v1 / (1.0f + __expf(-v1));
                uint2 pk;
                pk.x = f2tf32(h0 * sv + tv);
                pk.y = f2tf32(h1 * sv + tv);
                *(uint2*)(Hb + (size_t)o * HW + sc) = pk;
            }
        }
}

// ---------------------------------------------------------------------------
// K6: GEMM2. out = W2 @ H + b2 + x
// ---------------------------------------------------------------------------
__global__ void __launch_bounds__(256, 2)
k_gemm2(const float* __restrict__ b2,
        const float* __restrict__ x,
        float* __restrict__ out) {
    int b = blockIdx.z, tm = blockIdx.y, tn = blockIdx.x;
    int tid = threadIdx.x, lane = tid & 31, warp = tid >> 5;
    int wm = warp & 3, wn = warp >> 2;
    int g = lane >> 2, t = lane & 3;

    const uint32_t* Ag = g_W2t + (size_t)tm * 128 * CO;
    const uint32_t* Bg = g_H + (size_t)b * CO * HW + (size_t)tn * 128;

    Frag fr;
    gemm_mainloop<CO / 16>(dyn_smem, Ag, CO, Bg, fr, wm, wn, g, t, tid);

    const float* xb = x + (size_t)b * CC * HW;
    float* ob = out + (size_t)b * CC * HW;
    int row0 = tm * 128 + wm * 32;
    int col0 = tn * 128 + wn * 64;
#pragma unroll
    for (int mt = 0; mt < 2; mt++)
#pragma unroll
        for (int h2 = 0; h2 < 2; h2++) {
            int o = row0 + mt * 16 + h2 * 8 + g;
            float b2v = b2[o];
#pragma unroll
            for (int nt = 0; nt < 8; nt++) {
                int sc = col0 + nt * 8 + t * 2;
                float2 xr = *(const float2*)(xb + (size_t)o * HW + sc);
                float2 ov;
                ov.x = fr.acc[mt][nt][h2 * 2 + 0] + b2v + xr.x;
                ov.y = fr.acc[mt][nt][h2 * 2 + 1] + b2v + xr.y;
                *(float2*)(ob + (size_t)o * HW + sc) = ov;
            }
        }
}

// ---------------------------------------------------------------------------
extern "C" void kernel_launch(void* const* d_in, const int* in_sizes, int n_in,
                              void* d_out, int out_size) {
    const float* x    = (const float*)d_in[0];
    const float* emb  = (const float*)d_in[1];
    const float* gn_w = (const float*)d_in[2];
    const float* gn_b = (const float*)d_in[3];
    const float* w1   = (const float*)d_in[4];
    const float* b1   = (const float*)d_in[5];
    const float* we   = (const float*)d_in[6];
    const float* be   = (const float*)d_in[7];
    const float* w2   = (const float*)d_in[8];
    const float* b2   = (const float*)d_in[9];
    float* out = (float*)d_out;

    static bool attr_set = false;
    if (!attr_set) {
        cudaFuncSetAttribute(k_gemm1, cudaFuncAttributeMaxDynamicSharedMemorySize, SMEM_BYTES);
        cudaFuncSetAttribute(k_gemm2, cudaFuncAttributeMaxDynamicSharedMemorySize, SMEM_BYTES);
        attr_set = true;
    }

    k_gnstats<<<BB * NG, 256>>>(x, gn_w, gn_b);
    k_emb<<<(BB * CO) / 8, 256>>>(emb, we, be);
    k_prep<<<(2 * CO * CC / 4) / 256, 256>>>(w1, w2);
    k_norm<<<(BB * CC * HW / 4) / 256, 256>>>(x);
    k_gemm1<<<dim3(HW / 128, CO / 128, BB), 256, SMEM_BYTES>>>(b1);
    k_gemm2<<<dim3(HW / 128, CC / 128, BB), 256, SMEM_BYTES>>>(b2, x, out);
}

// round 5
// speedup vs baseline: 3.1022x; 1.5963x over previous
#include <cuda_runtime.h>
#include <cuda_fp16.h>
#include <cstdint>

// Problem constants
#define BB   16
#define CC   384      // C
#define CO   1536     // EXP*C
#define HW   1024     // 32*32
#define EMB_ 1024
#define NG   32
#define CPG  12
#define EPS_ 1e-5f

// ---------------- scratch (device globals) ---------------------------------
__device__ __align__(16) float  g_A[BB * CC];
__device__ __align__(16) float  g_D[BB * CC];
__device__ __align__(16) float  g_S[BB * CO];
__device__ __align__(16) float  g_T[BB * CO];
__device__ __align__(16) __half g_W1h[CO * CC];                // fp16 w1 [o][c]
__device__ __align__(16) __half g_W2h[CC * CO];                // fp16 w2 [o2][c']
__device__ __align__(16) __half g_Xnh[(size_t)BB * HW * CC];   // fp16 xn^T [b][s][c]
__device__ __align__(16) __half g_Hh[(size_t)BB * HW * CO];    // fp16 hidden [b][s][o]

// ---------------- helpers --------------------------------------------------
__device__ __forceinline__ void cpa16(uint32_t dst, const void* src) {
    asm volatile("cp.async.cg.shared.global [%0], [%1], 16;" :: "r"(dst), "l"(src));
}
#define CP_COMMIT() asm volatile("cp.async.commit_group;")
#define CP_WAIT3()  asm volatile("cp.async.wait_group 3;")

#define LDSM4(r0, r1, r2, r3, a)                                               \
    asm volatile("ldmatrix.sync.aligned.m8n8.x4.shared.b16 {%0,%1,%2,%3}, [%4];" \
        : "=r"(r0), "=r"(r1), "=r"(r2), "=r"(r3) : "r"(a))

#define MMA_F16(d, a, b)                                                       \
    asm volatile(                                                              \
        "mma.sync.aligned.m16n8k16.row.col.f32.f16.f16.f32 "                   \
        "{%0,%1,%2,%3},{%4,%5,%6,%7},{%8,%9},{%0,%1,%2,%3};\n"                 \
        : "+f"((d)[0]), "+f"((d)[1]), "+f"((d)[2]), "+f"((d)[3])               \
        : "r"((a)[0]), "r"((a)[1]), "r"((a)[2]), "r"((a)[3]),                  \
          "r"((b)[0]), "r"((b)[1]))

// ---------------------------------------------------------------------------
// K1: GroupNorm stats -> per-channel affine (A, D)
// ---------------------------------------------------------------------------
__global__ void k_gnstats(const float* __restrict__ x,
                          const float* __restrict__ gnw,
                          const float* __restrict__ gnb) {
    int bg = blockIdx.x;
    int b = bg >> 5;
    int gi = bg & 31;
    const float4* p = (const float4*)(x + ((size_t)b * CC + (size_t)gi * CPG) * HW);
    float s = 0.f, ss = 0.f;
#pragma unroll
    for (int i = 0; i < 12; i++) {
        float4 v = p[threadIdx.x + i * 256];
        s  += v.x + v.y + v.z + v.w;
        ss += v.x * v.x + v.y * v.y + v.z * v.z + v.w * v.w;
    }
#pragma unroll
    for (int off = 16; off; off >>= 1) {
        s  += __shfl_xor_sync(0xffffffffu, s, off);
        ss += __shfl_xor_sync(0xffffffffu, ss, off);
    }
    __shared__ float sh[64];
    int w = threadIdx.x >> 5, l = threadIdx.x & 31;
    if (l == 0) { sh[w] = s; sh[32 + w] = ss; }
    __syncthreads();
    if (threadIdx.x < CPG) {
        float S = 0.f, SS = 0.f;
#pragma unroll
        for (int i = 0; i < 8; i++) { S += sh[i]; SS += sh[32 + i]; }
        float mean = S * (1.0f / 12288.0f);
        float var  = SS * (1.0f / 12288.0f) - mean * mean;
        float rstd = rsqrtf(var + EPS_);
        int cch = gi * CPG + threadIdx.x;
        float wv = gnw[cch], bv = gnb[cch];
        g_A[b * CC + cch] = rstd * wv;
        g_D[b * CC + cch] = bv - mean * rstd * wv;
    }
}

// ---------------------------------------------------------------------------
// K2: emb_out = emb @ we.T + be  -> S = 1+scale, T = shift
// ---------------------------------------------------------------------------
__global__ void k_emb(const float* __restrict__ emb,
                      const float* __restrict__ we,
                      const float* __restrict__ be) {
    int task = blockIdx.x * 8 + (threadIdx.x >> 5);
    int lane = threadIdx.x & 31;
    int b = task / CO;
    int o = task - b * CO;
    const float4* e4 = (const float4*)(emb + (size_t)b * EMB_);
    const float4* wa = (const float4*)(we + (size_t)o * EMB_);
    const float4* wb = (const float4*)(we + (size_t)(o + CO) * EMB_);
    float s1 = 0.f, s2 = 0.f;
#pragma unroll
    for (int i = 0; i < 8; i++) {
        float4 ev = e4[lane + i * 32];
        float4 va = wa[lane + i * 32];
        float4 vb = wb[lane + i * 32];
        s1 += ev.x * va.x + ev.y * va.y + ev.z * va.z + ev.w * va.w;
        s2 += ev.x * vb.x + ev.y * vb.y + ev.z * vb.z + ev.w * vb.w;
    }
#pragma unroll
    for (int off = 16; off; off >>= 1) {
        s1 += __shfl_xor_sync(0xffffffffu, s1, off);
        s2 += __shfl_xor_sync(0xffffffffu, s2, off);
    }
    if (lane == 0) {
        g_S[task] = 1.0f + s1 + be[o];
        g_T[task] = s2 + be[o + CO];
    }
}

// ---------------------------------------------------------------------------
// K3: weights -> fp16
// ---------------------------------------------------------------------------
__global__ void k_prep(const float* __restrict__ w1,
                       const float* __restrict__ w2) {
    const int N1 = CO * CC / 4;
    int t = blockIdx.x * blockDim.x + threadIdx.x;
    const float4* src = (t < N1) ? (const float4*)w1 : (const float4*)w2;
    int i = (t < N1) ? t : t - N1;
    float4 v = src[i];
    __half2 lo = __floats2half2_rn(v.x, v.y);
    __half2 hi = __floats2half2_rn(v.z, v.w);
    uint2 pk = make_uint2(*(uint32_t*)&lo, *(uint32_t*)&hi);
    if (t < N1) ((uint2*)g_W1h)[i] = pk;
    else        ((uint2*)g_W2h)[i] = pk;
}

// ---------------------------------------------------------------------------
// K4: xn^T = fp16(A*x + D), transposed to [b][s][c]  (64x64 smem tiles)
// ---------------------------------------------------------------------------
__global__ void k_norm_t(const float* __restrict__ x) {
    __shared__ float sm[64][65];
    int b = blockIdx.z;
    int cg = blockIdx.y * 64;
    int sg = blockIdx.x * 64;
    int tid = threadIdx.x;
    int r = tid >> 2, q = tid & 3;
    float a = g_A[b * CC + cg + r];
    float d = g_D[b * CC + cg + r];
    const float* xr = x + ((size_t)b * CC + cg + r) * HW + sg + q * 16;
#pragma unroll
    for (int i = 0; i < 4; i++) {
        float4 v = *(const float4*)(xr + i * 4);
        sm[r][q * 16 + i * 4 + 0] = fmaf(a, v.x, d);
        sm[r][q * 16 + i * 4 + 1] = fmaf(a, v.y, d);
        sm[r][q * 16 + i * 4 + 2] = fmaf(a, v.z, d);
        sm[r][q * 16 + i * 4 + 3] = fmaf(a, v.w, d);
    }
    __syncthreads();
    __half* orow = g_Xnh + ((size_t)b * HW + sg + r) * CC + cg + q * 16;
#pragma unroll
    for (int i = 0; i < 4; i++) {
        __half2 lo = __floats2half2_rn(sm[q*16+i*4+0][r], sm[q*16+i*4+1][r]);
        __half2 hi = __floats2half2_rn(sm[q*16+i*4+2][r], sm[q*16+i*4+3][r]);
        *(uint2*)(orow + i * 4) = make_uint2(*(uint32_t*)&lo, *(uint32_t*)&hi);
    }
}

// ---------------------------------------------------------------------------
// GEMM core: CTA tile 128(M)x128(N), BK=32 fp16, 4-stage cp.async.
// Smem tiles: 128 rows x 32 halves (64B data), row pitch 80B (ldmatrix
// conflict-free: word pitch 20; 20*r mod 32 spans 8 distinct bank-quads).
// Both operands K-contiguous rows -> plain ldmatrix x4.
// ---------------------------------------------------------------------------
#define ROWPITCH 80
#define TILE_B   (128 * ROWPITCH)      // 10240 B per operand tile
#define STG_B    (2 * TILE_B)          // 20480 B per stage
#define SMEM_BYTES (4 * STG_B)         // 81920 B

extern __shared__ uint8_t dsm8[];

__device__ __forceinline__ void fill_stage(uint32_t sdst,
        const __half* Asrc, size_t lda, const __half* Bsrc, size_t ldb, int tid) {
#pragma unroll
    for (int i = 0; i < 4; i++) {
        int ch = tid + i * 256;            // 0..1023
        int isB = ch >> 9;                 // 512 chunks per operand
        int r   = (ch & 511) >> 2;
        int cb  = ch & 3;
        const __half* src = isB ? (Bsrc + (size_t)r * ldb + cb * 8)
                                : (Asrc + (size_t)r * lda + cb * 8);
        cpa16(sdst + isB * TILE_B + r * ROWPITCH + cb * 16, src);
    }
}

template <int KT>
__device__ __forceinline__ void gemm_mainloop(
        const __half* Abase, size_t lda, const __half* Bbase, size_t ldb,
        float acc[2][8][4], int tid) {
    const int lane = tid & 31, warp = tid >> 5;
    const int wm = warp & 3, wn = warp >> 2;
#pragma unroll
    for (int i = 0; i < 2; i++)
#pragma unroll
        for (int j = 0; j < 8; j++)
#pragma unroll
            for (int e = 0; e < 4; e++) acc[i][j][e] = 0.f;

    uint32_t smb = (uint32_t)__cvta_generic_to_shared(dsm8);

    // ldmatrix per-lane address offsets (bytes within tile)
    uint32_t aoff = (uint32_t)((wm * 32 + (lane & 15)) * ROWPITCH + (lane >> 4) * 16);
    uint32_t boff = (uint32_t)((wn * 64 + (lane & 7) + ((lane >> 4) << 3)) * ROWPITCH
                               + ((lane >> 3) & 1) * 16);

    // prologue: stages 0..2
#pragma unroll
    for (int s = 0; s < 3; s++) {
        fill_stage(smb + s * STG_B, Abase + s * 32, lda, Bbase + s * 32, ldb, tid);
        CP_COMMIT();
    }

    for (int kt = 0; kt < KT; kt++) {
        if (kt + 3 < KT)
            fill_stage(smb + ((kt + 3) & 3) * STG_B,
                       Abase + (size_t)(kt + 3) * 32, lda,
                       Bbase + (size_t)(kt + 3) * 32, ldb, tid);
        CP_COMMIT();
        CP_WAIT3();
        __syncthreads();

        uint32_t sA = smb + (kt & 3) * STG_B;
        uint32_t sB = sA + TILE_B;
#pragma unroll
        for (int kk = 0; kk < 2; kk++) {           // two k16 chunks
            uint32_t af[2][4], bf[8][2];
#pragma unroll
            for (int mt = 0; mt < 2; mt++)
                LDSM4(af[mt][0], af[mt][1], af[mt][2], af[mt][3],
                      sA + aoff + mt * 16 * ROWPITCH + kk * 32);
#pragma unroll
            for (int p = 0; p < 4; p++) {
                uint32_t r0, r1, r2, r3;
                LDSM4(r0, r1, r2, r3, sB + boff + p * 16 * ROWPITCH + kk * 32);
                bf[2 * p][0] = r0;  bf[2 * p][1] = r1;
                bf[2 * p + 1][0] = r2; bf[2 * p + 1][1] = r3;
            }
#pragma unroll
            for (int mt = 0; mt < 2; mt++)
#pragma unroll
                for (int nt = 0; nt < 8; nt++)
                    MMA_F16(acc[mt][nt], af[mt], bf[nt]);
        }
        __syncthreads();
    }
}

// ---------------------------------------------------------------------------
// K5: GEMM1: D[s,o] = xn^T[s,c] @ w1[o,c]^T; M=s,N=o,K=CC.
// epilogue: +b1, silu, *(1+scale)+shift -> H[b][s][o] fp16
// ---------------------------------------------------------------------------
__global__ void __launch_bounds__(256, 2)
k_gemm1(const float* __restrict__ b1) {
    __shared__ float sb1[128], sS[128], sT[128];
    const int tid = threadIdx.x;
    const int b = blockIdx.z;
    const int o0 = blockIdx.y * 128;
    const int s0 = blockIdx.x * 128;
    if (tid < 128) {
        int o = o0 + tid;
        sb1[tid] = b1[o];
        sS[tid]  = g_S[b * CO + o];
        sT[tid]  = g_T[b * CO + o];
    }

    const __half* Abase = g_Xnh + ((size_t)b * HW + s0) * CC;
    const __half* Bbase = g_W1h + (size_t)o0 * CC;
    float acc[2][8][4];
    gemm_mainloop<CC / 32>(Abase, CC, Bbase, CC, acc, tid);

    const int lane = tid & 31, warp = tid >> 5;
    const int wm = warp & 3, wn = warp >> 2;
    const int g = lane >> 2, t = lane & 3;
    __half* Hb = g_Hh + ((size_t)b * HW + s0) * CO + o0;
#pragma unroll
    for (int mt = 0; mt < 2; mt++)
#pragma unroll
        for (int h = 0; h < 2; h++) {
            int s_loc = wm * 32 + mt * 16 + h * 8 + g;
            __half* Hrow = Hb + (size_t)s_loc * CO;
#pragma unroll
            for (int nt = 0; nt < 8; nt++) {
                int oc = wn * 64 + nt * 8 + t * 2;
                float v0 = acc[mt][nt][h * 2 + 0] + sb1[oc];
                float v1 = acc[mt][nt][h * 2 + 1] + sb1[oc + 1];
                float h0 = v0 / (1.0f + __expf(-v0));
                float h1 = v1 / (1.0f + __expf(-v1));
                __half2 pk = __floats2half2_rn(h0 * sS[oc] + sT[oc],
                                               h1 * sS[oc + 1] + sT[oc + 1]);
                *(uint32_t*)(Hrow + oc) = *(uint32_t*)&pk;
            }
        }
}

// ---------------------------------------------------------------------------
// K6: GEMM2: D[o2,s] = w2[o2,c'] @ H[s,c']^T; M=o2,N=s,K=CO.
// epilogue: +b2 + residual x -> out[b][o2][s] (float2 coalesced)
// ---------------------------------------------------------------------------
__global__ void __launch_bounds__(256, 2)
k_gemm2(const float* __restrict__ b2,
        const float* __restrict__ x,
        float* __restrict__ out) {
    __shared__ float sb2[128];
    const int tid = threadIdx.x;
    const int b = blockIdx.z;
    const int o20 = blockIdx.y * 128;
    const int s0 = blockIdx.x * 128;
    if (tid < 128) sb2[tid] = b2[o20 + tid];

    const __half* Abase = g_W2h + (size_t)o20 * CO;
    const __half* Bbase = g_Hh + ((size_t)b * HW + s0) * CO;
    float acc[2][8][4];
    gemm_mainloop<CO / 32>(Abase, CO, Bbase, CO, acc, tid);

    const int lane = tid & 31, warp = tid >> 5;
    const int wm = warp & 3, wn = warp >> 2;
    const int g = lane >> 2, t = lane & 3;
    const float* xb = x + (size_t)b * CC * HW + s0;
    float* ob = out + (size_t)b * CC * HW + s0;
#pragma unroll
    for (int mt = 0; mt < 2; mt++)
#pragma unroll
        for (int h = 0; h < 2; h++) {
            int o2 = o20 + wm * 32 + mt * 16 + h * 8 + g;
            float bv = sb2[wm * 32 + mt * 16 + h * 8 + g];
            const float* xrow = xb + (size_t)(o2 - o20 + o20) * HW;  // = x + o2*HW + s0
            float* orow = ob + (size_t)(o2 - o20 + o20) * HW;
            // simplify: recompute directly
            xrow = x + (size_t)b * CC * HW + (size_t)o2 * HW + s0;
            orow = out + (size_t)b * CC * HW + (size_t)o2 * HW + s0;
#pragma unroll
            for (int nt = 0; nt < 8; nt++) {
                int sc = wn * 64 + nt * 8 + t * 2;
                float2 xr = *(const float2*)(xrow + sc);
                float2 ov;
                ov.x = acc[mt][nt][h * 2 + 0] + bv + xr.x;
                ov.y = acc[mt][nt][h * 2 + 1] + bv + xr.y;
                *(float2*)(orow + sc) = ov;
            }
        }
}

// ---------------------------------------------------------------------------
extern "C" void kernel_launch(void* const* d_in, const int* in_sizes, int n_in,
                              void* d_out, int out_size) {
    const float* x    = (const float*)d_in[0];
    const float* emb  = (const float*)d_in[1];
    const float* gn_w = (const float*)d_in[2];
    const float* gn_b = (const float*)d_in[3];
    const float* w1   = (const float*)d_in[4];
    const float* b1   = (const float*)d_in[5];
    const float* we   = (const float*)d_in[6];
    const float* be   = (const float*)d_in[7];
    const float* w2   = (const float*)d_in[8];
    const float* b2   = (const float*)d_in[9];
    float* out = (float*)d_out;

    static bool attr_set = false;
    if (!attr_set) {
        cudaFuncSetAttribute(k_gemm1, cudaFuncAttributeMaxDynamicSharedMemorySize, SMEM_BYTES);
        cudaFuncSetAttribute(k_gemm2, cudaFuncAttributeMaxDynamicSharedMemorySize, SMEM_BYTES);
        attr_set = true;
    }

    k_gnstats<<<BB * NG, 256>>>(x, gn_w, gn_b);
    k_emb<<<(BB * CO) / 8, 256>>>(emb, we, be);
    k_prep<<<(2 * CO * CC / 4) / 256, 256>>>(w1, w2);
    k_norm_t<<<dim3(HW / 64, CC / 64, BB), 256>>>(x);
    k_gemm1<<<dim3(HW / 128, CO / 128, BB), 256, SMEM_BYTES>>>(b1);
    k_gemm2<<<dim3(HW / 128, CC / 128, BB), 256, SMEM_BYTES>>>(b2, x, out);
}